// round 1
// baseline (speedup 1.0000x reference)
#include <cuda_runtime.h>
#include <math.h>

// Batched log(A) for SPD 64x64 via Chebyshev/Clenshaw matrix polynomial.
// Spectrum of A = W W^T/64 + 0.1 I is in [0.1, ~4.8]; we approximate log on
// [0.09, 5.3] with degree-36 Chebyshev (closed-form coefficients), evaluated
// with the Clenshaw recurrence: one 64x64x64 fp32 matmul per step, all in smem.

#define DEG 36
#define NN  64

__global__ __launch_bounds__(256, 4)
void logm_cheb_kernel(const float* __restrict__ A, float* __restrict__ Out)
{
    __shared__ __align__(16) float Ah[NN * NN];        // scaled Ahat (symmetric)
    __shared__ __align__(16) float Bb[2][NN * NN];     // Clenshaw b1 / b2

    const int tid = threadIdx.x;
    const int mat = blockIdx.x;

    const float lo  = 0.09f, hi = 5.30f;
    const float h   = 0.5f * (hi - lo);
    const float mid = 0.5f * (hi + lo);
    const float u   = mid / h;
    const float rho = u + sqrtf(u * u - 1.0f);
    const float alpha = 1.0f / h;          // t = alpha*x - u

    // c_k = 2*(-1)^{k+1} / (k * rho^k),  c_0 = log(h*rho/2)
    const float cK   = ((DEG & 1) ? 2.0f : -2.0f) * powf(rho, -(float)DEG) / (float)DEG;
    const float cKm1 = (((DEG - 1) & 1) ? 2.0f : -2.0f) * powf(rho, -(float)(DEG - 1)) / (float)(DEG - 1);
    const float c0   = logf(h * rho * 0.5f);

    // ---- Load A, build Ahat = alpha*A - u*I, and init Clenshaw state ----
    // b_K   = cK * I
    // b_K-1 = cKm1 * I + 2*cK*Ahat
    {
        const float4* Ag = (const float4*)(A + (size_t)mat * (NN * NN));
        float4* Ah4 = (float4*)Ah;
        float4* B04 = (float4*)Bb[0];
        float4* B14 = (float4*)Bb[1];
        #pragma unroll
        for (int r = 0; r < 4; ++r) {
            int q = tid + r * 256;          // float4 index, 0..1023
            float4 v = Ag[q];
            int e = q << 2;
            int i = e >> 6;
            int j = e & 63;
            float dx = (j + 0 == i) ? 1.0f : 0.0f;
            float dy = (j + 1 == i) ? 1.0f : 0.0f;
            float dz = (j + 2 == i) ? 1.0f : 0.0f;
            float dw = (j + 3 == i) ? 1.0f : 0.0f;
            v.x = alpha * v.x - u * dx;
            v.y = alpha * v.y - u * dy;
            v.z = alpha * v.z - u * dz;
            v.w = alpha * v.w - u * dw;
            Ah4[q] = v;
            float4 b0, b1;
            b0.x = 2.0f * cK * v.x + cKm1 * dx;
            b0.y = 2.0f * cK * v.y + cKm1 * dy;
            b0.z = 2.0f * cK * v.z + cKm1 * dz;
            b0.w = 2.0f * cK * v.w + cKm1 * dw;
            b1.x = cK * dx;  b1.y = cK * dy;  b1.z = cK * dz;  b1.w = cK * dw;
            B04[q] = b0;
            B14[q] = b1;
        }
    }
    __syncthreads();

    // Thread tile: 4x4 outputs. rows i0..i0+3, cols j0..j0+3
    const int i0 = (tid >> 4) << 2;
    const int j0 = (tid & 15) << 2;

    int cur = 0;                            // index of b_{k+1}
    float rp = powf(rho, -(float)(DEG - 2)); // rho^{-k} tracker

    for (int k = DEG - 2; k >= 0; --k) {
        const int oth = cur ^ 1;
        const float* __restrict__ Bc = Bb[cur];

        float acc[4][4] = {{0.f,0.f,0.f,0.f},{0.f,0.f,0.f,0.f},
                           {0.f,0.f,0.f,0.f},{0.f,0.f,0.f,0.f}};
        // C = Ahat * b1.  Ahat is symmetric: Ah[kk*64 + i] == Ahat[i][kk],
        // so both operands stream row-contiguous (LDS.128 friendly).
        #pragma unroll 16
        for (int kk = 0; kk < NN; ++kk) {
            float4 av = *(const float4*)(Ah + kk * NN + i0);
            float4 bv = *(const float4*)(Bc + kk * NN + j0);
            acc[0][0] += av.x * bv.x; acc[0][1] += av.x * bv.y;
            acc[0][2] += av.x * bv.z; acc[0][3] += av.x * bv.w;
            acc[1][0] += av.y * bv.x; acc[1][1] += av.y * bv.y;
            acc[1][2] += av.y * bv.z; acc[1][3] += av.y * bv.w;
            acc[2][0] += av.z * bv.x; acc[2][1] += av.z * bv.y;
            acc[2][2] += av.z * bv.z; acc[2][3] += av.z * bv.w;
            acc[3][0] += av.w * bv.x; acc[3][1] += av.w * bv.y;
            acc[3][2] += av.w * bv.z; acc[3][3] += av.w * bv.w;
        }

        if (k >= 1) {
            const float ck = ((k & 1) ? 2.0f : -2.0f) * rp / (float)k;
            float* __restrict__ Bo = Bb[oth];
            #pragma unroll
            for (int r = 0; r < 4; ++r) {
                const int row = i0 + r;
                float4 p = *(const float4*)(Bo + row * NN + j0);
                float4 o;
                o.x = 2.0f * acc[r][0] - p.x + ((row == j0 + 0) ? ck : 0.0f);
                o.y = 2.0f * acc[r][1] - p.y + ((row == j0 + 1) ? ck : 0.0f);
                o.z = 2.0f * acc[r][2] - p.z + ((row == j0 + 2) ? ck : 0.0f);
                o.w = 2.0f * acc[r][3] - p.w + ((row == j0 + 3) ? ck : 0.0f);
                *(float4*)(Bo + row * NN + j0) = o;
            }
            rp *= rho;
            cur = oth;
            __syncthreads();
        } else {
            // final: out = Ahat*b1 - b2 + c0*I
            float* __restrict__ Og = Out + (size_t)mat * (NN * NN);
            const float* __restrict__ Bo = Bb[oth];
            #pragma unroll
            for (int r = 0; r < 4; ++r) {
                const int row = i0 + r;
                float4 p = *(const float4*)(Bo + row * NN + j0);
                float4 o;
                o.x = acc[r][0] - p.x + ((row == j0 + 0) ? c0 : 0.0f);
                o.y = acc[r][1] - p.y + ((row == j0 + 1) ? c0 : 0.0f);
                o.z = acc[r][2] - p.z + ((row == j0 + 2) ? c0 : 0.0f);
                o.w = acc[r][3] - p.w + ((row == j0 + 3) ? c0 : 0.0f);
                *(float4*)(Og + row * NN + j0) = o;
            }
        }
    }
}

extern "C" void kernel_launch(void* const* d_in, const int* in_sizes, int n_in,
                              void* d_out, int out_size) {
    const float* x = (const float*)d_in[0];
    float* out = (float*)d_out;
    int nmat = in_sizes[0] / (NN * NN);
    logm_cheb_kernel<<<nmat, 256>>>(x, out);
}